// round 3
// baseline (speedup 1.0000x reference)
#include <cuda_runtime.h>
#include <cuda_bf16.h>
#include <math.h>

// Problem constants
#define NN 512
#define DIM 384
#define PDIM 128
#define H 8
#define SK 16
#define SV 16
#define PK 4
#define PV 8
#define PROJ_COLS 768           // 128+128+128+96+96+192
#define RES_COLS 1408           // 128 + 192 + 64 + 1024
#define EPSV 1e-8f

__device__ __constant__ float kScaleScalar = 0.14433756729740643f;  // (3*16)^-0.5
__device__ __constant__ float kScalePoint  = 0.13608276348795434f;  // (3*4*4.5)^-0.5
__device__ __constant__ float kScalePair   = 0.57735026918962576f;  // 3^-0.5

// Scratch (allocation-free contract: __device__ globals)
__device__ float g_Wcat[DIM * PROJ_COLS];
__device__ float g_proj[NN * PROJ_COLS];
__device__ float g_qpg[NN * H * PK * 3];
__device__ float g_kpg[NN * H * PK * 3];
__device__ float g_vpg[NN * H * PV * 3];
__device__ float g_res[NN * RES_COLS];

// ---------------------------------------------------------------------------
// Kernel 1: concat projection weights into [384 x 768]
// ---------------------------------------------------------------------------
__global__ void concat_w_kernel(const float* __restrict__ Wsq, const float* __restrict__ Wsk,
                                const float* __restrict__ Wsv, const float* __restrict__ Wpq,
                                const float* __restrict__ Wpk, const float* __restrict__ Wpv)
{
    int idx = blockIdx.x * blockDim.x + threadIdx.x;
    if (idx >= DIM * PROJ_COLS) return;
    int k = idx / PROJ_COLS;
    int c = idx - k * PROJ_COLS;
    float v;
    if (c < 128)       v = Wsq[k * 128 + c];
    else if (c < 256)  v = Wsk[k * 128 + (c - 128)];
    else if (c < 384)  v = Wsv[k * 128 + (c - 256)];
    else if (c < 480)  v = Wpq[k * 96 + (c - 384)];
    else if (c < 576)  v = Wpk[k * 96 + (c - 480)];
    else               v = Wpv[k * 192 + (c - 576)];
    g_Wcat[idx] = v;
}

// ---------------------------------------------------------------------------
// 64x64 tiled fp32 GEMM, 4x4 microtile, BK=16.  C (+)= A[M,K] * B[K,N].
// ---------------------------------------------------------------------------
__global__ __launch_bounds__(256) void gemm64_kernel(const float* __restrict__ A,
                                                     const float* __restrict__ B,
                                                     float* __restrict__ C,
                                                     int M, int N, int K,
                                                     int kChunk, int useAtomic)
{
    __shared__ float As[16][68];   // [k][m]
    __shared__ float Bs[16][68];   // [k][n]
    const int bm = blockIdx.y * 64;
    const int bn = blockIdx.x * 64;
    int k0 = blockIdx.z * kChunk;
    int k1 = k0 + kChunk; if (k1 > K) k1 = K;
    const int t  = threadIdx.x;
    const int tx = t & 15, ty = t >> 4;

    const int lm  = t >> 2;          // A row 0..63
    const int lk4 = (t & 3) * 4;     // A k offset 0,4,8,12
    const int lkb = t >> 4;          // B k row 0..15
    const int lnb = (t & 15) * 4;    // B n offset

    float acc[4][4];
    #pragma unroll
    for (int r = 0; r < 4; r++)
        #pragma unroll
        for (int c = 0; c < 4; c++) acc[r][c] = 0.f;

    for (int kt = k0; kt < k1; kt += 16) {
        float4 a4 = *(const float4*)&A[(size_t)(bm + lm) * K + kt + lk4];
        float4 b4 = *(const float4*)&B[(size_t)(kt + lkb) * N + bn + lnb];
        __syncthreads();
        As[lk4 + 0][lm] = a4.x; As[lk4 + 1][lm] = a4.y;
        As[lk4 + 2][lm] = a4.z; As[lk4 + 3][lm] = a4.w;
        *(float4*)&Bs[lkb][lnb] = b4;
        __syncthreads();
        #pragma unroll
        for (int kk = 0; kk < 16; kk++) {
            float4 av = *(const float4*)&As[kk][ty * 4];
            float4 bv = *(const float4*)&Bs[kk][tx * 4];
            acc[0][0] += av.x * bv.x; acc[0][1] += av.x * bv.y; acc[0][2] += av.x * bv.z; acc[0][3] += av.x * bv.w;
            acc[1][0] += av.y * bv.x; acc[1][1] += av.y * bv.y; acc[1][2] += av.y * bv.z; acc[1][3] += av.y * bv.w;
            acc[2][0] += av.z * bv.x; acc[2][1] += av.z * bv.y; acc[2][2] += av.z * bv.z; acc[2][3] += av.z * bv.w;
            acc[3][0] += av.w * bv.x; acc[3][1] += av.w * bv.y; acc[3][2] += av.w * bv.z; acc[3][3] += av.w * bv.w;
        }
    }
    #pragma unroll
    for (int r = 0; r < 4; r++) {
        float* cp = &C[(size_t)(bm + ty * 4 + r) * N + bn + tx * 4];
        if (useAtomic) {
            atomicAdd(cp + 0, acc[r][0]); atomicAdd(cp + 1, acc[r][1]);
            atomicAdd(cp + 2, acc[r][2]); atomicAdd(cp + 3, acc[r][3]);
        } else {
            float4 v; v.x = acc[r][0]; v.y = acc[r][1]; v.z = acc[r][2]; v.w = acc[r][3];
            *(float4*)cp = v;
        }
    }
}

// ---------------------------------------------------------------------------
// Kernel 3: rotate+translate point projections to global frame.
// ---------------------------------------------------------------------------
__global__ void transform_kernel(const float* __restrict__ rot, const float* __restrict__ trans)
{
    int pid = blockIdx.x * blockDim.x + threadIdx.x;
    if (pid >= 65536) return;
    int n;
    const float* src;
    float* dst;
    if (pid < 16384) {
        n = pid >> 5; int pd = pid & 31;
        src = g_proj + n * PROJ_COLS + 384 + pd * 3;
        dst = g_qpg + n * 96 + pd * 3;
    } else if (pid < 32768) {
        int p = pid - 16384;
        n = p >> 5; int pd = p & 31;
        src = g_proj + n * PROJ_COLS + 480 + pd * 3;
        dst = g_kpg + n * 96 + pd * 3;
    } else {
        int p = pid - 32768;
        n = p >> 6; int pd = p & 63;
        src = g_proj + n * PROJ_COLS + 576 + pd * 3;
        dst = g_vpg + n * 192 + pd * 3;
    }
    float p0 = src[0], p1 = src[1], p2 = src[2];
    const float* R = rot + n * 9;
    const float* tt = trans + n * 3;
    dst[0] = p0 * R[0] + p1 * R[3] + p2 * R[6] + tt[0];
    dst[1] = p0 * R[1] + p1 * R[4] + p2 * R[7] + tt[1];
    dst[2] = p0 * R[2] + p1 * R[5] + p2 * R[8] + tt[2];
}

// ---------------------------------------------------------------------------
// Kernel 4: fused single-pass attention with online softmax.
// One block per query i. Per 32-j tile:
//   stage pair tile -> logits (all warps, reg-resident Wpair) -> online
//   softmax update -> accumulate res_pair/res_scalar/res_point (rescaled).
// Pairwise is read from DRAM exactly once.
// ---------------------------------------------------------------------------
__global__ __launch_bounds__(256) void attn_kernel(const float* __restrict__ pairw,
                                                   const float* __restrict__ rot,
                                                   const float* __restrict__ trans,
                                                   const float* __restrict__ point_weights,
                                                   const float* __restrict__ Wpair,
                                                   const float* __restrict__ bpair)
{
    const int i = blockIdx.x;
    const int t = threadIdx.x;
    const int w = t >> 5, lane = t & 31;
    const int h = lane >> 2, s = lane & 3;

    __shared__ float4 sPair4[32][33];        // 32 j x 32 float4, pad 1
    __shared__ float  sTileL[8][36];         // per-tile logits -> weights
    __shared__ float  sM[8], sSum[8], sScale[8];

    // --- register-resident per-(h,s) slices ---
    float Wreg[32];
    #pragma unroll
    for (int k = 0; k < 32; k++) Wreg[k] = Wpair[(s + 4 * k) * 8 + h];
    float qs[4];
    #pragma unroll
    for (int e = 0; e < 4; e++) qs[e] = g_proj[i * PROJ_COLS + h * 16 + s + 4 * e];
    float qp[3];
    #pragma unroll
    for (int e = 0; e < 3; e++) qp[e] = g_qpg[i * 96 + h * 12 + s + 4 * e];
    const float spw = log1pf(__expf(point_weights[h]));
    const float cP = -0.5f * spw * kScalePoint;
    const float biasH = bpair[h] * kScalePair;

    // --- accumulators (role depends on warp) ---
    float4 accP0 = make_float4(0.f, 0.f, 0.f, 0.f);   // t<128: res_pair head 2hp
    float4 accP1 = make_float4(0.f, 0.f, 0.f, 0.f);   //        res_pair head 2hp+1
    float accVp0 = 0.f, accVp1 = 0.f, accVp2 = 0.f;   // t in [128,192): point vec
    float accVs0 = 0.f, accVs1 = 0.f;                 // t in [192,256): scalar v

    if (t < 8) { sM[t] = -1e30f; sSum[t] = 0.f; }

    const float* pairRow = pairw + (size_t)i * NN * PDIM;
    const float* sPairF = (const float*)sPair4;       // float pitch 132 per jj

    for (int jt = 0; jt < NN; jt += 32) {
        __syncthreads();                 // protect sPair from previous accum
        // ---- stage pair tile (32 x 128 floats) ----
        {
            int jj = t >> 3, dq = t & 7;
            const float4* src = (const float4*)(pairRow + (size_t)(jt + jj) * PDIM) + dq;
            float4* dst = &sPair4[jj][dq];
            #pragma unroll
            for (int kk = 0; kk < 4; kk++) dst[kk * 8] = src[kk * 8];
        }
        __syncthreads();
        // ---- logits: warp w computes j = jt + w*4 + q ----
        #pragma unroll
        for (int q = 0; q < 4; q++) {
            const int jj = (w << 2) + q;
            const int j = jt + jj;
            const float* pr = sPairF + jj * 132 + s;
            float b0 = 0.f, b1 = 0.f;
            #pragma unroll
            for (int k = 0; k < 32; k += 2) {
                b0 += pr[4 * k]     * Wreg[k];
                b1 += pr[4 * k + 4] * Wreg[k + 1];
            }
            float accB = b0 + b1;
            const float* ks = g_proj + j * PROJ_COLS + 128 + h * 16 + s;
            float accS = 0.f;
            #pragma unroll
            for (int e = 0; e < 4; e++) accS += qs[e] * ks[4 * e];
            const float* kp = g_kpg + j * 96 + h * 12 + s;
            float accPt = 0.f;
            #pragma unroll
            for (int e = 0; e < 3; e++) { float d = qp[e] - kp[4 * e]; accPt += d * d; }
            float part = accB * kScalePair + accS * kScaleScalar + accPt * cP;
            part += __shfl_xor_sync(0xffffffffu, part, 1);
            part += __shfl_xor_sync(0xffffffffu, part, 2);
            if (s == 0) sTileL[h][jj] = part + biasH;
        }
        __syncthreads();
        // ---- online softmax update: warp w owns head w ----
        {
            float l = sTileL[w][lane];
            float tm = l;
            #pragma unroll
            for (int o = 16; o; o >>= 1) tm = fmaxf(tm, __shfl_xor_sync(0xffffffffu, tm, o));
            float mOld = sM[w];
            float mNew = fmaxf(mOld, tm);
            float wgt = __expf(l - mNew);
            sTileL[w][lane] = wgt;
            float ts = wgt;
            #pragma unroll
            for (int o = 16; o; o >>= 1) ts += __shfl_xor_sync(0xffffffffu, ts, o);
            if (lane == 0) {
                float sc = __expf(mOld - mNew);
                sScale[w] = sc;
                sSum[w] = sSum[w] * sc + ts;
                sM[w] = mNew;
            }
        }
        __syncthreads();
        // ---- accumulate ----
        if (t < 128) {
            const int d4 = t & 31, hp = t >> 5;      // heads 2hp, 2hp+1
            const float sc0 = sScale[2 * hp], sc1 = sScale[2 * hp + 1];
            accP0.x *= sc0; accP0.y *= sc0; accP0.z *= sc0; accP0.w *= sc0;
            accP1.x *= sc1; accP1.y *= sc1; accP1.z *= sc1; accP1.w *= sc1;
            const float* w0p = &sTileL[2 * hp][0];
            const float* w1p = &sTileL[2 * hp + 1][0];
            #pragma unroll 4
            for (int jj = 0; jj < 32; jj++) {
                float w0 = w0p[jj], w1 = w1p[jj];
                float4 p = sPair4[jj][d4];
                accP0.x += w0 * p.x; accP0.y += w0 * p.y; accP0.z += w0 * p.z; accP0.w += w0 * p.w;
                accP1.x += w1 * p.x; accP1.y += w1 * p.y; accP1.z += w1 * p.z; accP1.w += w1 * p.w;
            }
        } else if (t < 192) {
            const int u = t - 128;
            const int hh = u >> 3, pv = u & 7;
            const float sc = sScale[hh];
            accVp0 *= sc; accVp1 *= sc; accVp2 *= sc;
            const float* vp = g_vpg + (size_t)jt * 192 + hh * 24 + pv * 3;
            const float* wp = &sTileL[hh][0];
            #pragma unroll 4
            for (int jj = 0; jj < 32; jj++) {
                float wg = wp[jj];
                accVp0 += wg * vp[jj * 192 + 0];
                accVp1 += wg * vp[jj * 192 + 1];
                accVp2 += wg * vp[jj * 192 + 2];
            }
        } else {
            const int u = t - 192;
            const int hh = u >> 3, c = u & 7;
            const float sc = sScale[hh];
            accVs0 *= sc; accVs1 *= sc;
            const float* vs = g_proj + (size_t)jt * PROJ_COLS + 256 + hh * 16 + c;
            const float* wp = &sTileL[hh][0];
            #pragma unroll 4
            for (int jj = 0; jj < 32; jj++) {
                float wg = wp[jj];
                accVs0 += wg * vs[jj * PROJ_COLS];
                accVs1 += wg * vs[jj * PROJ_COLS + 8];
            }
        }
    }
    __syncthreads();

    // ---- epilogue: normalize + write results row ----
    float* resRow = g_res + (size_t)i * RES_COLS;
    if (t < 128) {
        const int d4 = t & 31, hp = t >> 5;
        const float inv0 = 1.f / sSum[2 * hp];
        const float inv1 = 1.f / sSum[2 * hp + 1];
        float4 o0, o1;
        o0.x = accP0.x * inv0; o0.y = accP0.y * inv0; o0.z = accP0.z * inv0; o0.w = accP0.w * inv0;
        o1.x = accP1.x * inv1; o1.y = accP1.y * inv1; o1.z = accP1.z * inv1; o1.w = accP1.w * inv1;
        *((float4*)(resRow + 384 + (2 * hp) * 128) + d4) = o0;
        *((float4*)(resRow + 384 + (2 * hp + 1) * 128) + d4) = o1;
    } else if (t < 192) {
        const int u = t - 128;
        const int hh = u >> 3, pv = u & 7;
        const float inv = 1.f / sSum[hh];
        float g0 = accVp0 * inv - trans[i * 3 + 0];
        float g1 = accVp1 * inv - trans[i * 3 + 1];
        float g2 = accVp2 * inv - trans[i * 3 + 2];
        const float* R = rot + i * 9;
        float n2 = EPSV;
        #pragma unroll
        for (int r = 0; r < 3; r++) {
            float lr = g0 * R[r * 3 + 0] + g1 * R[r * 3 + 1] + g2 * R[r * 3 + 2];
            resRow[128 + hh * 24 + pv * 3 + r] = lr;
            n2 += lr * lr;
        }
        resRow[320 + hh * 8 + pv] = sqrtf(n2);
    } else {
        const int u = t - 192;
        const int hh = u >> 3, c = u & 7;
        const float inv = 1.f / sSum[hh];
        resRow[hh * 16 + c] = accVs0 * inv;
        resRow[hh * 16 + c + 8] = accVs1 * inv;
    }
}

// ---------------------------------------------------------------------------
// Kernel 5: init output with bias
// ---------------------------------------------------------------------------
__global__ void init_out_kernel(float* __restrict__ out, const float* __restrict__ bout)
{
    int idx = blockIdx.x * blockDim.x + threadIdx.x;
    if (idx < NN * DIM) out[idx] = bout[idx % DIM];
}

// ---------------------------------------------------------------------------
extern "C" void kernel_launch(void* const* d_in, const int* in_sizes, int n_in,
                              void* d_out, int out_size)
{
    const float* x      = (const float*)d_in[0];
    const float* pairw  = (const float*)d_in[1];
    const float* rot    = (const float*)d_in[2];
    const float* trans  = (const float*)d_in[3];
    const float* Wsq    = (const float*)d_in[4];
    const float* Wsk    = (const float*)d_in[5];
    const float* Wsv    = (const float*)d_in[6];
    const float* Wpq    = (const float*)d_in[7];
    const float* Wpk    = (const float*)d_in[8];
    const float* Wpv    = (const float*)d_in[9];
    const float* pw     = (const float*)d_in[10];
    const float* Wpair  = (const float*)d_in[11];
    const float* bpair  = (const float*)d_in[12];
    const float* Wout   = (const float*)d_in[13];
    const float* bout   = (const float*)d_in[14];
    float* out = (float*)d_out;

    float *pWcat, *pProj, *pRes;
    cudaGetSymbolAddress((void**)&pWcat, g_Wcat);
    cudaGetSymbolAddress((void**)&pProj, g_proj);
    cudaGetSymbolAddress((void**)&pRes,  g_res);

    // 1. concat weights
    concat_w_kernel<<<(DIM * PROJ_COLS + 255) / 256, 256>>>(Wsq, Wsk, Wsv, Wpq, Wpk, Wpv);

    // 2. projections: proj[512,768] = x[512,384] @ Wcat[384,768]
    gemm64_kernel<<<dim3(PROJ_COLS / 64, NN / 64, 1), 256>>>(x, pWcat, pProj,
                                                             NN, PROJ_COLS, DIM, DIM, 0);

    // 3. transform points to global frame
    transform_kernel<<<65536 / 256, 256>>>(rot, trans);

    // 4. fused single-pass attention
    attn_kernel<<<NN, 256>>>(pairw, rot, trans, pw, Wpair, bpair);

    // 5. init output with bias
    init_out_kernel<<<(NN * DIM + 255) / 256, 256>>>(out, bout);

    // 6. out += res[512,1408] @ Wout[1408,384], split-K=4 with atomics
    gemm64_kernel<<<dim3(DIM / 64, NN / 64, 4), 256>>>(pRes, Wout, out,
                                                       NN, DIM, RES_COLS, 352, 1);
}

// round 4
// speedup vs baseline: 1.0130x; 1.0130x over previous
#include <cuda_runtime.h>
#include <cuda_bf16.h>
#include <math.h>

// Problem constants
#define NN 512
#define DIM 384
#define PDIM 128
#define H 8
#define SK 16
#define SV 16
#define PK 4
#define PV 8
#define PROJ_COLS 768           // 128+128+128+96+96+192
#define RES_COLS 1408           // 128 + 192 + 64 + 1024
#define EPSV 1e-8f

__device__ __constant__ float kScaleScalar = 0.14433756729740643f;  // (3*16)^-0.5
__device__ __constant__ float kScalePoint  = 0.13608276348795434f;  // (3*4*4.5)^-0.5
__device__ __constant__ float kScalePair   = 0.57735026918962576f;  // 3^-0.5

// Scratch (allocation-free contract: __device__ globals)
__device__ float g_Wcat[DIM * PROJ_COLS];
__device__ float g_proj[NN * PROJ_COLS];
__device__ float g_qpg[NN * H * PK * 3];
__device__ float g_kpg[NN * H * PK * 3];
__device__ float g_vpg[NN * H * PV * 3];
__device__ float g_res[NN * RES_COLS];

// ---------------------------------------------------------------------------
// Kernel 1: concat projection weights into [384 x 768]
// ---------------------------------------------------------------------------
__global__ void concat_w_kernel(const float* __restrict__ Wsq, const float* __restrict__ Wsk,
                                const float* __restrict__ Wsv, const float* __restrict__ Wpq,
                                const float* __restrict__ Wpk, const float* __restrict__ Wpv)
{
    int idx = blockIdx.x * blockDim.x + threadIdx.x;
    if (idx >= DIM * PROJ_COLS) return;
    int k = idx / PROJ_COLS;
    int c = idx - k * PROJ_COLS;
    float v;
    if (c < 128)       v = Wsq[k * 128 + c];
    else if (c < 256)  v = Wsk[k * 128 + (c - 128)];
    else if (c < 384)  v = Wsv[k * 128 + (c - 256)];
    else if (c < 480)  v = Wpq[k * 96 + (c - 384)];
    else if (c < 576)  v = Wpk[k * 96 + (c - 480)];
    else               v = Wpv[k * 192 + (c - 576)];
    g_Wcat[idx] = v;
}

// ---------------------------------------------------------------------------
// 64x64 tiled fp32 GEMM, 4x4 microtile, BK=16.  C (+)= A[M,K] * B[K,N].
// ---------------------------------------------------------------------------
__global__ __launch_bounds__(256) void gemm64_kernel(const float* __restrict__ A,
                                                     const float* __restrict__ B,
                                                     float* __restrict__ C,
                                                     int M, int N, int K,
                                                     int kChunk, int useAtomic)
{
    __shared__ float As[16][68];   // [k][m]
    __shared__ float Bs[16][68];   // [k][n]
    const int bm = blockIdx.y * 64;
    const int bn = blockIdx.x * 64;
    int k0 = blockIdx.z * kChunk;
    int k1 = k0 + kChunk; if (k1 > K) k1 = K;
    const int t  = threadIdx.x;
    const int tx = t & 15, ty = t >> 4;

    const int lm  = t >> 2;          // A row 0..63
    const int lk4 = (t & 3) * 4;     // A k offset 0,4,8,12
    const int lkb = t >> 4;          // B k row 0..15
    const int lnb = (t & 15) * 4;    // B n offset

    float acc[4][4];
    #pragma unroll
    for (int r = 0; r < 4; r++)
        #pragma unroll
        for (int c = 0; c < 4; c++) acc[r][c] = 0.f;

    for (int kt = k0; kt < k1; kt += 16) {
        float4 a4 = *(const float4*)&A[(size_t)(bm + lm) * K + kt + lk4];
        float4 b4 = *(const float4*)&B[(size_t)(kt + lkb) * N + bn + lnb];
        __syncthreads();
        As[lk4 + 0][lm] = a4.x; As[lk4 + 1][lm] = a4.y;
        As[lk4 + 2][lm] = a4.z; As[lk4 + 3][lm] = a4.w;
        *(float4*)&Bs[lkb][lnb] = b4;
        __syncthreads();
        #pragma unroll
        for (int kk = 0; kk < 16; kk++) {
            float4 av = *(const float4*)&As[kk][ty * 4];
            float4 bv = *(const float4*)&Bs[kk][tx * 4];
            acc[0][0] += av.x * bv.x; acc[0][1] += av.x * bv.y; acc[0][2] += av.x * bv.z; acc[0][3] += av.x * bv.w;
            acc[1][0] += av.y * bv.x; acc[1][1] += av.y * bv.y; acc[1][2] += av.y * bv.z; acc[1][3] += av.y * bv.w;
            acc[2][0] += av.z * bv.x; acc[2][1] += av.z * bv.y; acc[2][2] += av.z * bv.z; acc[2][3] += av.z * bv.w;
            acc[3][0] += av.w * bv.x; acc[3][1] += av.w * bv.y; acc[3][2] += av.w * bv.z; acc[3][3] += av.w * bv.w;
        }
    }
    #pragma unroll
    for (int r = 0; r < 4; r++) {
        float* cp = &C[(size_t)(bm + ty * 4 + r) * N + bn + tx * 4];
        if (useAtomic) {
            atomicAdd(cp + 0, acc[r][0]); atomicAdd(cp + 1, acc[r][1]);
            atomicAdd(cp + 2, acc[r][2]); atomicAdd(cp + 3, acc[r][3]);
        } else {
            float4 v; v.x = acc[r][0]; v.y = acc[r][1]; v.z = acc[r][2]; v.w = acc[r][3];
            *(float4*)cp = v;
        }
    }
}

// ---------------------------------------------------------------------------
// Kernel 3: rotate+translate point projections to global frame.
// ---------------------------------------------------------------------------
__global__ void transform_kernel(const float* __restrict__ rot, const float* __restrict__ trans)
{
    int pid = blockIdx.x * blockDim.x + threadIdx.x;
    if (pid >= 65536) return;
    int n;
    const float* src;
    float* dst;
    if (pid < 16384) {
        n = pid >> 5; int pd = pid & 31;
        src = g_proj + n * PROJ_COLS + 384 + pd * 3;
        dst = g_qpg + n * 96 + pd * 3;
    } else if (pid < 32768) {
        int p = pid - 16384;
        n = p >> 5; int pd = p & 31;
        src = g_proj + n * PROJ_COLS + 480 + pd * 3;
        dst = g_kpg + n * 96 + pd * 3;
    } else {
        int p = pid - 32768;
        n = p >> 6; int pd = p & 63;
        src = g_proj + n * PROJ_COLS + 576 + pd * 3;
        dst = g_vpg + n * 192 + pd * 3;
    }
    float p0 = src[0], p1 = src[1], p2 = src[2];
    const float* R = rot + n * 9;
    const float* tt = trans + n * 3;
    dst[0] = p0 * R[0] + p1 * R[3] + p2 * R[6] + tt[0];
    dst[1] = p0 * R[1] + p1 * R[4] + p2 * R[7] + tt[1];
    dst[2] = p0 * R[2] + p1 * R[5] + p2 * R[8] + tt[2];
}

// ---------------------------------------------------------------------------
// Kernel 4: fused single-pass attention with online softmax.
// One block per query i. Per 32-j tile:
//   stage pair tile -> logits (all warps, reg-resident Wpair) -> online
//   softmax update -> accumulate res_pair/res_scalar/res_point (rescaled).
// Pairwise is read from DRAM exactly once.
// ---------------------------------------------------------------------------
__global__ __launch_bounds__(256) void attn_kernel(const float* __restrict__ pairw,
                                                   const float* __restrict__ rot,
                                                   const float* __restrict__ trans,
                                                   const float* __restrict__ point_weights,
                                                   const float* __restrict__ Wpair,
                                                   const float* __restrict__ bpair)
{
    const int i = blockIdx.x;
    const int t = threadIdx.x;
    const int w = t >> 5, lane = t & 31;
    const int h = lane >> 2, s = lane & 3;

    __shared__ float4 sPair4[32][33];        // 32 j x 32 float4, pad 1
    __shared__ float  sTileL[8][36];         // per-tile logits -> weights
    __shared__ float  sM[8], sSum[8], sScale[8];

    // --- register-resident per-(h,s) slices ---
    float Wreg[32];
    #pragma unroll
    for (int k = 0; k < 32; k++) Wreg[k] = Wpair[(s + 4 * k) * 8 + h];
    float qs[4];
    #pragma unroll
    for (int e = 0; e < 4; e++) qs[e] = g_proj[i * PROJ_COLS + h * 16 + s + 4 * e];
    float qp[3];
    #pragma unroll
    for (int e = 0; e < 3; e++) qp[e] = g_qpg[i * 96 + h * 12 + s + 4 * e];
    const float spw = log1pf(__expf(point_weights[h]));
    const float cP = -0.5f * spw * kScalePoint;
    const float biasH = bpair[h] * kScalePair;

    // --- accumulators (role depends on warp) ---
    float4 accP0 = make_float4(0.f, 0.f, 0.f, 0.f);   // t<128: res_pair head 2hp
    float4 accP1 = make_float4(0.f, 0.f, 0.f, 0.f);   //        res_pair head 2hp+1
    float accVp0 = 0.f, accVp1 = 0.f, accVp2 = 0.f;   // t in [128,192): point vec
    float accVs0 = 0.f, accVs1 = 0.f;                 // t in [192,256): scalar v

    if (t < 8) { sM[t] = -1e30f; sSum[t] = 0.f; }

    const float* pairRow = pairw + (size_t)i * NN * PDIM;
    const float* sPairF = (const float*)sPair4;       // float pitch 132 per jj

    for (int jt = 0; jt < NN; jt += 32) {
        __syncthreads();                 // protect sPair from previous accum
        // ---- stage pair tile (32 x 128 floats) ----
        {
            int jj = t >> 3, dq = t & 7;
            const float4* src = (const float4*)(pairRow + (size_t)(jt + jj) * PDIM) + dq;
            float4* dst = &sPair4[jj][dq];
            #pragma unroll
            for (int kk = 0; kk < 4; kk++) dst[kk * 8] = src[kk * 8];
        }
        __syncthreads();
        // ---- logits: warp w computes j = jt + w*4 + q ----
        #pragma unroll
        for (int q = 0; q < 4; q++) {
            const int jj = (w << 2) + q;
            const int j = jt + jj;
            const float* pr = sPairF + jj * 132 + s;
            float b0 = 0.f, b1 = 0.f;
            #pragma unroll
            for (int k = 0; k < 32; k += 2) {
                b0 += pr[4 * k]     * Wreg[k];
                b1 += pr[4 * k + 4] * Wreg[k + 1];
            }
            float accB = b0 + b1;
            const float* ks = g_proj + j * PROJ_COLS + 128 + h * 16 + s;
            float accS = 0.f;
            #pragma unroll
            for (int e = 0; e < 4; e++) accS += qs[e] * ks[4 * e];
            const float* kp = g_kpg + j * 96 + h * 12 + s;
            float accPt = 0.f;
            #pragma unroll
            for (int e = 0; e < 3; e++) { float d = qp[e] - kp[4 * e]; accPt += d * d; }
            float part = accB * kScalePair + accS * kScaleScalar + accPt * cP;
            part += __shfl_xor_sync(0xffffffffu, part, 1);
            part += __shfl_xor_sync(0xffffffffu, part, 2);
            if (s == 0) sTileL[h][jj] = part + biasH;
        }
        __syncthreads();
        // ---- online softmax update: warp w owns head w ----
        {
            float l = sTileL[w][lane];
            float tm = l;
            #pragma unroll
            for (int o = 16; o; o >>= 1) tm = fmaxf(tm, __shfl_xor_sync(0xffffffffu, tm, o));
            float mOld = sM[w];
            float mNew = fmaxf(mOld, tm);
            float wgt = __expf(l - mNew);
            sTileL[w][lane] = wgt;
            float ts = wgt;
            #pragma unroll
            for (int o = 16; o; o >>= 1) ts += __shfl_xor_sync(0xffffffffu, ts, o);
            if (lane == 0) {
                float sc = __expf(mOld - mNew);
                sScale[w] = sc;
                sSum[w] = sSum[w] * sc + ts;
                sM[w] = mNew;
            }
        }
        __syncthreads();
        // ---- accumulate ----
        if (t < 128) {
            const int d4 = t & 31, hp = t >> 5;      // heads 2hp, 2hp+1
            const float sc0 = sScale[2 * hp], sc1 = sScale[2 * hp + 1];
            accP0.x *= sc0; accP0.y *= sc0; accP0.z *= sc0; accP0.w *= sc0;
            accP1.x *= sc1; accP1.y *= sc1; accP1.z *= sc1; accP1.w *= sc1;
            const float* w0p = &sTileL[2 * hp][0];
            const float* w1p = &sTileL[2 * hp + 1][0];
            #pragma unroll 4
            for (int jj = 0; jj < 32; jj++) {
                float w0 = w0p[jj], w1 = w1p[jj];
                float4 p = sPair4[jj][d4];
                accP0.x += w0 * p.x; accP0.y += w0 * p.y; accP0.z += w0 * p.z; accP0.w += w0 * p.w;
                accP1.x += w1 * p.x; accP1.y += w1 * p.y; accP1.z += w1 * p.z; accP1.w += w1 * p.w;
            }
        } else if (t < 192) {
            const int u = t - 128;
            const int hh = u >> 3, pv = u & 7;
            const float sc = sScale[hh];
            accVp0 *= sc; accVp1 *= sc; accVp2 *= sc;
            const float* vp = g_vpg + (size_t)jt * 192 + hh * 24 + pv * 3;
            const float* wp = &sTileL[hh][0];
            #pragma unroll 4
            for (int jj = 0; jj < 32; jj++) {
                float wg = wp[jj];
                accVp0 += wg * vp[jj * 192 + 0];
                accVp1 += wg * vp[jj * 192 + 1];
                accVp2 += wg * vp[jj * 192 + 2];
            }
        } else {
            const int u = t - 192;
            const int hh = u >> 3, c = u & 7;
            const float sc = sScale[hh];
            accVs0 *= sc; accVs1 *= sc;
            const float* vs = g_proj + (size_t)jt * PROJ_COLS + 256 + hh * 16 + c;
            const float* wp = &sTileL[hh][0];
            #pragma unroll 4
            for (int jj = 0; jj < 32; jj++) {
                float wg = wp[jj];
                accVs0 += wg * vs[jj * PROJ_COLS];
                accVs1 += wg * vs[jj * PROJ_COLS + 8];
            }
        }
    }
    __syncthreads();

    // ---- epilogue: normalize + write results row ----
    float* resRow = g_res + (size_t)i * RES_COLS;
    if (t < 128) {
        const int d4 = t & 31, hp = t >> 5;
        const float inv0 = 1.f / sSum[2 * hp];
        const float inv1 = 1.f / sSum[2 * hp + 1];
        float4 o0, o1;
        o0.x = accP0.x * inv0; o0.y = accP0.y * inv0; o0.z = accP0.z * inv0; o0.w = accP0.w * inv0;
        o1.x = accP1.x * inv1; o1.y = accP1.y * inv1; o1.z = accP1.z * inv1; o1.w = accP1.w * inv1;
        *((float4*)(resRow + 384 + (2 * hp) * 128) + d4) = o0;
        *((float4*)(resRow + 384 + (2 * hp + 1) * 128) + d4) = o1;
    } else if (t < 192) {
        const int u = t - 128;
        const int hh = u >> 3, pv = u & 7;
        const float inv = 1.f / sSum[hh];
        float g0 = accVp0 * inv - trans[i * 3 + 0];
        float g1 = accVp1 * inv - trans[i * 3 + 1];
        float g2 = accVp2 * inv - trans[i * 3 + 2];
        const float* R = rot + i * 9;
        float n2 = EPSV;
        #pragma unroll
        for (int r = 0; r < 3; r++) {
            float lr = g0 * R[r * 3 + 0] + g1 * R[r * 3 + 1] + g2 * R[r * 3 + 2];
            resRow[128 + hh * 24 + pv * 3 + r] = lr;
            n2 += lr * lr;
        }
        resRow[320 + hh * 8 + pv] = sqrtf(n2);
    } else {
        const int u = t - 192;
        const int hh = u >> 3, c = u & 7;
        const float inv = 1.f / sSum[hh];
        resRow[hh * 16 + c] = accVs0 * inv;
        resRow[hh * 16 + c + 8] = accVs1 * inv;
    }
}

// ---------------------------------------------------------------------------
// Kernel 5: init output with bias
// ---------------------------------------------------------------------------
__global__ void init_out_kernel(float* __restrict__ out, const float* __restrict__ bout)
{
    int idx = blockIdx.x * blockDim.x + threadIdx.x;
    if (idx < NN * DIM) out[idx] = bout[idx % DIM];
}

// ---------------------------------------------------------------------------
extern "C" void kernel_launch(void* const* d_in, const int* in_sizes, int n_in,
                              void* d_out, int out_size)
{
    const float* x      = (const float*)d_in[0];
    const float* pairw  = (const float*)d_in[1];
    const float* rot    = (const float*)d_in[2];
    const float* trans  = (const float*)d_in[3];
    const float* Wsq    = (const float*)d_in[4];
    const float* Wsk    = (const float*)d_in[5];
    const float* Wsv    = (const float*)d_in[6];
    const float* Wpq    = (const float*)d_in[7];
    const float* Wpk    = (const float*)d_in[8];
    const float* Wpv    = (const float*)d_in[9];
    const float* pw     = (const float*)d_in[10];
    const float* Wpair  = (const float*)d_in[11];
    const float* bpair  = (const float*)d_in[12];
    const float* Wout   = (const float*)d_in[13];
    const float* bout   = (const float*)d_in[14];
    float* out = (float*)d_out;

    float *pWcat, *pProj, *pRes;
    cudaGetSymbolAddress((void**)&pWcat, g_Wcat);
    cudaGetSymbolAddress((void**)&pProj, g_proj);
    cudaGetSymbolAddress((void**)&pRes,  g_res);

    // 1. concat weights
    concat_w_kernel<<<(DIM * PROJ_COLS + 255) / 256, 256>>>(Wsq, Wsk, Wsv, Wpq, Wpk, Wpv);

    // 2. projections: proj[512,768] = x[512,384] @ Wcat[384,768]
    gemm64_kernel<<<dim3(PROJ_COLS / 64, NN / 64, 1), 256>>>(x, pWcat, pProj,
                                                             NN, PROJ_COLS, DIM, DIM, 0);

    // 3. transform points to global frame
    transform_kernel<<<65536 / 256, 256>>>(rot, trans);

    // 4. fused single-pass attention
    attn_kernel<<<NN, 256>>>(pairw, rot, trans, pw, Wpair, bpair);

    // 5. init output with bias
    init_out_kernel<<<(NN * DIM + 255) / 256, 256>>>(out, bout);

    // 6. out += res[512,1408] @ Wout[1408,384], split-K=4 with atomics
    gemm64_kernel<<<dim3(DIM / 64, NN / 64, 4), 256>>>(pRes, Wout, out,
                                                       NN, DIM, RES_COLS, 352, 1);
}